// round 12
// baseline (speedup 1.0000x reference)
#include <cuda_runtime.h>

#define S_LEN 2048
#define E_DIM 1024
#define NHEAD 16
#define DHEAD 64
#define BATCH 2
#define MROWS 4096   // BATCH * S_LEN
#define KDIM  1024

// ---------------- scratch (allocation-free) ----------------
__device__ float g_Qp[BATCH * NHEAD * S_LEN * DHEAD];  // [b][h][s][d]
__device__ float g_Kp[BATCH * NHEAD * S_LEN * DHEAD];
__device__ float g_Vp[BATCH * NHEAD * S_LEN * DHEAD];
__device__ float g_ctx[BATCH * S_LEN * E_DIM];         // [b][s][e]

// =====================================================================
// Fused QKV projection GEMM.
// grid (24, 32): blockIdx.x selects 128-col slab of the 3072-wide Wqkv;
// slice = bx>>3 picks input (q/k/v) and output buffer (Qp/Kp/Vp).
// 128x128 tile, BK=16, 256 threads, 8x8 microtile, double-buffered.
// Output written in head-split layout [b][h][s][d].
// =====================================================================
__global__ __launch_bounds__(256, 2) void sgemm_qkv_kernel(
    const float* __restrict__ q, const float* __restrict__ k,
    const float* __restrict__ v, const float* __restrict__ W,
    const float* __restrict__ bias,
    float* __restrict__ Qp, float* __restrict__ Kp, float* __restrict__ Vp)
{
    __shared__ float sA[2][16 * 132];
    __shared__ float sB[2][16 * 128];

    const int tid = threadIdx.x;
    const int tx = tid & 15, ty = tid >> 4;
    const int m0 = blockIdx.y << 7;
    const int bx = blockIdx.x;
    const int slice = bx >> 3;
    const int n0 = bx << 7;                 // global col into [0,3072)
    const int ldw = 3 * E_DIM;

    const float* X  = (slice == 0) ? q : (slice == 1) ? k : v;
    float* out      = (slice == 0) ? Qp : (slice == 1) ? Kp : Vp;

    const int aR0 = tid >> 2,         aC0 = (tid & 3) << 2;
    const int aR1 = (tid + 256) >> 2, aC1 = aC0;
    const int bR0 = tid >> 5,         bC0 = (tid & 31) << 2;
    const int bR1 = bR0 + 8,          bC1 = bC0;

    float acc[8][8];
    #pragma unroll
    for (int i = 0; i < 8; i++)
        #pragma unroll
        for (int j = 0; j < 8; j++) acc[i][j] = 0.f;

    float4 ra0, ra1, rb0, rb1;
    ra0 = *reinterpret_cast<const float4*>(&X[(m0 + aR0) * KDIM + aC0]);
    ra1 = *reinterpret_cast<const float4*>(&X[(m0 + aR1) * KDIM + aC1]);
    rb0 = *reinterpret_cast<const float4*>(&W[bR0 * ldw + n0 + bC0]);
    rb1 = *reinterpret_cast<const float4*>(&W[bR1 * ldw + n0 + bC1]);
    {
        float* p0 = &sA[0][aC0 * 132 + aR0];
        p0[0] = ra0.x; p0[132] = ra0.y; p0[264] = ra0.z; p0[396] = ra0.w;
        float* p1 = &sA[0][aC1 * 132 + aR1];
        p1[0] = ra1.x; p1[132] = ra1.y; p1[264] = ra1.z; p1[396] = ra1.w;
        *reinterpret_cast<float4*>(&sB[0][bR0 * 128 + bC0]) = rb0;
        *reinterpret_cast<float4*>(&sB[0][bR1 * 128 + bC1]) = rb1;
    }
    __syncthreads();

    int buf = 0;
    const int NSTEPS = KDIM / 16;
    for (int s = 0; s < NSTEPS; s++) {
        if (s + 1 < NSTEPS) {
            const int kn = (s + 1) << 4;
            ra0 = *reinterpret_cast<const float4*>(&X[(m0 + aR0) * KDIM + kn + aC0]);
            ra1 = *reinterpret_cast<const float4*>(&X[(m0 + aR1) * KDIM + kn + aC1]);
            rb0 = *reinterpret_cast<const float4*>(&W[(kn + bR0) * ldw + n0 + bC0]);
            rb1 = *reinterpret_cast<const float4*>(&W[(kn + bR1) * ldw + n0 + bC1]);
        }
        const float* pa = &sA[buf][ty << 3];
        const float* pb = &sB[buf][tx << 3];
        #pragma unroll 8
        for (int kk = 0; kk < 16; kk++) {
            float4 a0 = *reinterpret_cast<const float4*>(&pa[kk * 132]);
            float4 a1 = *reinterpret_cast<const float4*>(&pa[kk * 132 + 4]);
            float4 b0 = *reinterpret_cast<const float4*>(&pb[kk * 128]);
            float4 b1 = *reinterpret_cast<const float4*>(&pb[kk * 128 + 4]);
            float av[8] = {a0.x, a0.y, a0.z, a0.w, a1.x, a1.y, a1.z, a1.w};
            float bv[8] = {b0.x, b0.y, b0.z, b0.w, b1.x, b1.y, b1.z, b1.w};
            #pragma unroll
            for (int i = 0; i < 8; i++)
                #pragma unroll
                for (int j = 0; j < 8; j++)
                    acc[i][j] = fmaf(av[i], bv[j], acc[i][j]);
        }
        if (s + 1 < NSTEPS) {
            const int nb = buf ^ 1;
            float* p0 = &sA[nb][aC0 * 132 + aR0];
            p0[0] = ra0.x; p0[132] = ra0.y; p0[264] = ra0.z; p0[396] = ra0.w;
            float* p1 = &sA[nb][aC1 * 132 + aR1];
            p1[0] = ra1.x; p1[132] = ra1.y; p1[264] = ra1.z; p1[396] = ra1.w;
            *reinterpret_cast<float4*>(&sB[nb][bR0 * 128 + bC0]) = rb0;
            *reinterpret_cast<float4*>(&sB[nb][bR1 * 128 + bC1]) = rb1;
        }
        __syncthreads();
        buf ^= 1;
    }

    #pragma unroll
    for (int i = 0; i < 8; i++) {
        const int m  = m0 + (ty << 3) + i;
        const int bb = m >> 11;
        const int sq = m & (S_LEN - 1);
        #pragma unroll
        for (int j = 0; j < 8; j++) {
            const int n = n0 + (tx << 3) + j;
            const float val = acc[i][j] + bias[n];
            const int ns = n - (slice << 10);     // col within 1024 slice
            const int hh = ns >> 6, dd = ns & 63;
            out[((bb * NHEAD + hh) * S_LEN + sq) * DHEAD + dd] = val;
        }
    }
}

// =====================================================================
// Output projection GEMM: out = ctx[4096,1024] @ Wout[1024,1024] + bout.
// =====================================================================
__global__ __launch_bounds__(256, 2) void sgemm_out_kernel(
    const float* __restrict__ X, const float* __restrict__ W,
    const float* __restrict__ bias, float* __restrict__ out)
{
    __shared__ float sA[2][16 * 132];
    __shared__ float sB[2][16 * 128];

    const int tid = threadIdx.x;
    const int tx = tid & 15, ty = tid >> 4;
    const int m0 = blockIdx.y << 7;
    const int n0 = blockIdx.x << 7;
    const int ldw = E_DIM;

    const int aR0 = tid >> 2,         aC0 = (tid & 3) << 2;
    const int aR1 = (tid + 256) >> 2, aC1 = aC0;
    const int bR0 = tid >> 5,         bC0 = (tid & 31) << 2;
    const int bR1 = bR0 + 8,          bC1 = bC0;

    float acc[8][8];
    #pragma unroll
    for (int i = 0; i < 8; i++)
        #pragma unroll
        for (int j = 0; j < 8; j++) acc[i][j] = 0.f;

    float4 ra0, ra1, rb0, rb1;
    ra0 = *reinterpret_cast<const float4*>(&X[(m0 + aR0) * KDIM + aC0]);
    ra1 = *reinterpret_cast<const float4*>(&X[(m0 + aR1) * KDIM + aC1]);
    rb0 = *reinterpret_cast<const float4*>(&W[bR0 * ldw + n0 + bC0]);
    rb1 = *reinterpret_cast<const float4*>(&W[bR1 * ldw + n0 + bC1]);
    {
        float* p0 = &sA[0][aC0 * 132 + aR0];
        p0[0] = ra0.x; p0[132] = ra0.y; p0[264] = ra0.z; p0[396] = ra0.w;
        float* p1 = &sA[0][aC1 * 132 + aR1];
        p1[0] = ra1.x; p1[132] = ra1.y; p1[264] = ra1.z; p1[396] = ra1.w;
        *reinterpret_cast<float4*>(&sB[0][bR0 * 128 + bC0]) = rb0;
        *reinterpret_cast<float4*>(&sB[0][bR1 * 128 + bC1]) = rb1;
    }
    __syncthreads();

    int buf = 0;
    const int NSTEPS = KDIM / 16;
    for (int s = 0; s < NSTEPS; s++) {
        if (s + 1 < NSTEPS) {
            const int kn = (s + 1) << 4;
            ra0 = *reinterpret_cast<const float4*>(&X[(m0 + aR0) * KDIM + kn + aC0]);
            ra1 = *reinterpret_cast<const float4*>(&X[(m0 + aR1) * KDIM + kn + aC1]);
            rb0 = *reinterpret_cast<const float4*>(&W[(kn + bR0) * ldw + n0 + bC0]);
            rb1 = *reinterpret_cast<const float4*>(&W[(kn + bR1) * ldw + n0 + bC1]);
        }
        const float* pa = &sA[buf][ty << 3];
        const float* pb = &sB[buf][tx << 3];
        #pragma unroll 8
        for (int kk = 0; kk < 16; kk++) {
            float4 a0 = *reinterpret_cast<const float4*>(&pa[kk * 132]);
            float4 a1 = *reinterpret_cast<const float4*>(&pa[kk * 132 + 4]);
            float4 b0 = *reinterpret_cast<const float4*>(&pb[kk * 128]);
            float4 b1 = *reinterpret_cast<const float4*>(&pb[kk * 128 + 4]);
            float av[8] = {a0.x, a0.y, a0.z, a0.w, a1.x, a1.y, a1.z, a1.w};
            float bv[8] = {b0.x, b0.y, b0.z, b0.w, b1.x, b1.y, b1.z, b1.w};
            #pragma unroll
            for (int i = 0; i < 8; i++)
                #pragma unroll
                for (int j = 0; j < 8; j++)
                    acc[i][j] = fmaf(av[i], bv[j], acc[i][j]);
        }
        if (s + 1 < NSTEPS) {
            const int nb = buf ^ 1;
            float* p0 = &sA[nb][aC0 * 132 + aR0];
            p0[0] = ra0.x; p0[132] = ra0.y; p0[264] = ra0.z; p0[396] = ra0.w;
            float* p1 = &sA[nb][aC1 * 132 + aR1];
            p1[0] = ra1.x; p1[132] = ra1.y; p1[264] = ra1.z; p1[396] = ra1.w;
            *reinterpret_cast<float4*>(&sB[nb][bR0 * 128 + bC0]) = rb0;
            *reinterpret_cast<float4*>(&sB[nb][bR1 * 128 + bC1]) = rb1;
        }
        __syncthreads();
        buf ^= 1;
    }

    #pragma unroll
    for (int i = 0; i < 8; i++) {
        const int m = m0 + (ty << 3) + i;
        #pragma unroll
        for (int j = 0; j < 8; j++) {
            const int n = n0 + (tx << 3) + j;
            out[m * E_DIM + n] = acc[i][j] + bias[n];
        }
    }
}

// =====================================================================
// Flash attention v2: grid (S/128, H, B), 256 threads.
// Q-tile 128 x K-tile 64, 8x4 microtiles (32 S-accums + 32 O-accums).
// =====================================================================
#define PADQ 132
#define PADK 68
#define ATTN_SMEM ((2 * 64 * PADQ + 2 * 64 * PADK) * (int)sizeof(float))  // 102400

__global__ __launch_bounds__(256, 2) void attn_kernel(
    const float* __restrict__ Qp, const float* __restrict__ Kp,
    const float* __restrict__ Vp, const int* __restrict__ mask,
    float* __restrict__ ctx)
{
    extern __shared__ float smem[];
    float* Qt = smem;                               // [d][q] 64 x PADQ
    float* Ps = smem + 64 * PADQ;                   // [j][i] 64 x PADQ
    float* Kt = smem + 2 * 64 * PADQ;               // [d][j] 64 x PADK
    float* Vs = smem + 2 * 64 * PADQ + 64 * PADK;   // [j][d] 64 x PADK

    const int tid = threadIdx.x;
    const int tx = tid & 15, ty = tid >> 4;   // tx: 4 K-cols, ty: 8 Q-rows
    const int q0 = blockIdx.x << 7;
    const int h  = blockIdx.y, b = blockIdx.z;
    const int base = ((b * NHEAD + h) * S_LEN) * DHEAD;

    // stage Q transposed once: Qt[d][s], 128 rows
    {
        const int d = tid & 63, sg = (tid >> 6) << 5;
        #pragma unroll
        for (int blk = 0; blk < 32; blk += 4) {
            const int s = q0 + sg + blk;
            float t0 = Qp[base + (s + 0) * DHEAD + d];
            float t1 = Qp[base + (s + 1) * DHEAD + d];
            float t2 = Qp[base + (s + 2) * DHEAD + d];
            float t3 = Qp[base + (s + 3) * DHEAD + d];
            *reinterpret_cast<float4*>(&Qt[d * PADQ + sg + blk]) = make_float4(t0, t1, t2, t3);
        }
    }

    float o[8][4];
    #pragma unroll
    for (int i = 0; i < 8; i++) { o[i][0] = o[i][1] = o[i][2] = o[i][3] = 0.f; }
    float mrow[8], lrow[8];
    #pragma unroll
    for (int i = 0; i < 8; i++) { mrow[i] = -1e30f; lrow[i] = 0.f; }

    for (int kt = 0; kt < S_LEN / 64; kt++) {
        const int k0 = kt << 6;
        __syncthreads();  // previous readers of Kt/Vs/Ps done

        // stage K transposed
        {
            const int d = tid & 63, sg = (tid >> 6) << 4;
            #pragma unroll
            for (int blk = 0; blk < 16; blk += 4) {
                const int s = k0 + sg + blk;
                float t0 = Kp[base + (s + 0) * DHEAD + d];
                float t1 = Kp[base + (s + 1) * DHEAD + d];
                float t2 = Kp[base + (s + 2) * DHEAD + d];
                float t3 = Kp[base + (s + 3) * DHEAD + d];
                *reinterpret_cast<float4*>(&Kt[d * PADK + sg + blk]) = make_float4(t0, t1, t2, t3);
            }
        }
        // stage V natural
        #pragma unroll
        for (int r = 0; r < 4; r++) {
            const int idx = tid + (r << 8);
            const int srow = idx >> 4, c = (idx & 15) << 2;
            float4 vv = *reinterpret_cast<const float4*>(&Vp[base + (k0 + srow) * DHEAD + c]);
            *reinterpret_cast<float4*>(&Vs[srow * PADK + c]) = vv;
        }
        __syncthreads();

        // S = Q @ K^T, 8x4 microtile
        float sa[8][4];
        #pragma unroll
        for (int i = 0; i < 8; i++) { sa[i][0] = sa[i][1] = sa[i][2] = sa[i][3] = 0.f; }
        #pragma unroll 4
        for (int kk = 0; kk < 64; kk++) {
            float4 a0 = *reinterpret_cast<const float4*>(&Qt[kk * PADQ + (ty << 3)]);
            float4 a1 = *reinterpret_cast<const float4*>(&Qt[kk * PADQ + (ty << 3) + 4]);
            float4 bk = *reinterpret_cast<const float4*>(&Kt[kk * PADK + (tx << 2)]);
            float av[8] = {a0.x, a0.y, a0.z, a0.w, a1.x, a1.y, a1.z, a1.w};
            float bv[4] = {bk.x, bk.y, bk.z, bk.w};
            #pragma unroll
            for (int i = 0; i < 8; i++)
                #pragma unroll
                for (int j = 0; j < 4; j++)
                    sa[i][j] = fmaf(av[i], bv[j], sa[i][j]);
        }

        // mask + scale (1/sqrt(64) = 0.125)
        #pragma unroll
        for (int ii = 0; ii < 8; ii++) {
            const int4 mv = *reinterpret_cast<const int4*>(
                &mask[(q0 + (ty << 3) + ii) * S_LEN + k0 + (tx << 2)]);
            sa[ii][0] = mv.x ? sa[ii][0] * 0.125f : -1e30f;
            sa[ii][1] = mv.y ? sa[ii][1] * 0.125f : -1e30f;
            sa[ii][2] = mv.z ? sa[ii][2] * 0.125f : -1e30f;
            sa[ii][3] = mv.w ? sa[ii][3] * 0.125f : -1e30f;
        }

        // online softmax per row (row spread over 16 tx lanes)
        #pragma unroll
        for (int ii = 0; ii < 8; ii++) {
            float tm = fmaxf(fmaxf(sa[ii][0], sa[ii][1]), fmaxf(sa[ii][2], sa[ii][3]));
            tm = fmaxf(tm, __shfl_xor_sync(0xffffffffu, tm, 8));
            tm = fmaxf(tm, __shfl_xor_sync(0xffffffffu, tm, 4));
            tm = fmaxf(tm, __shfl_xor_sync(0xffffffffu, tm, 2));
            tm = fmaxf(tm, __shfl_xor_sync(0xffffffffu, tm, 1));
            const float mn = fmaxf(mrow[ii], tm);
            const float corr = __expf(mrow[ii] - mn);
            mrow[ii] = mn;
            float ps = 0.f;
            #pragma unroll
            for (int jj = 0; jj < 4; jj++) {
                sa[ii][jj] = __expf(sa[ii][jj] - mn);
                ps += sa[ii][jj];
            }
            ps += __shfl_xor_sync(0xffffffffu, ps, 8);
            ps += __shfl_xor_sync(0xffffffffu, ps, 4);
            ps += __shfl_xor_sync(0xffffffffu, ps, 2);
            ps += __shfl_xor_sync(0xffffffffu, ps, 1);
            lrow[ii] = lrow[ii] * corr + ps;
            o[ii][0] *= corr; o[ii][1] *= corr; o[ii][2] *= corr; o[ii][3] *= corr;
        }

        // store P transposed: Ps[j][i]
        #pragma unroll
        for (int jj = 0; jj < 4; jj++) {
            *reinterpret_cast<float4*>(&Ps[((tx << 2) + jj) * PADQ + (ty << 3)]) =
                make_float4(sa[0][jj], sa[1][jj], sa[2][jj], sa[3][jj]);
            *reinterpret_cast<float4*>(&Ps[((tx << 2) + jj) * PADQ + (ty << 3) + 4]) =
                make_float4(sa[4][jj], sa[5][jj], sa[6][jj], sa[7][jj]);
        }
        __syncthreads();

        // O += P @ V, 8x4 microtile
        #pragma unroll 4
        for (int kk = 0; kk < 64; kk++) {
            float4 p0 = *reinterpret_cast<const float4*>(&Ps[kk * PADQ + (ty << 3)]);
            float4 p1 = *reinterpret_cast<const float4*>(&Ps[kk * PADQ + (ty << 3) + 4]);
            float4 vv = *reinterpret_cast<const float4*>(&Vs[kk * PADK + (tx << 2)]);
            float pv[8] = {p0.x, p0.y, p0.z, p0.w, p1.x, p1.y, p1.z, p1.w};
            float vb[4] = {vv.x, vv.y, vv.z, vv.w};
            #pragma unroll
            for (int i = 0; i < 8; i++)
                #pragma unroll
                for (int j = 0; j < 4; j++)
                    o[i][j] = fmaf(pv[i], vb[j], o[i][j]);
        }
    }

    // normalize + write ctx [b][s][e], e = h*64 + d
    #pragma unroll
    for (int ii = 0; ii < 8; ii++) {
        const float inv = 1.f / lrow[ii];
        const int row = q0 + (ty << 3) + ii;
        float4 w = make_float4(o[ii][0] * inv, o[ii][1] * inv, o[ii][2] * inv, o[ii][3] * inv);
        *reinterpret_cast<float4*>(&ctx[(b * S_LEN + row) * E_DIM + h * DHEAD + (tx << 2)]) = w;
    }
}

// =====================================================================
extern "C" void kernel_launch(void* const* d_in, const int* in_sizes, int n_in,
                              void* d_out, int out_size)
{
    const float* q    = (const float*)d_in[0];
    const float* k    = (const float*)d_in[1];
    const float* v    = (const float*)d_in[2];
    const int*   mask = (const int*)  d_in[3];
    const float* Wqkv = (const float*)d_in[4];
    const float* bqkv = (const float*)d_in[5];
    const float* Wout = (const float*)d_in[6];
    const float* bout = (const float*)d_in[7];
    float* out = (float*)d_out;
    (void)in_sizes; (void)n_in; (void)out_size;

    float *Qp, *Kp, *Vp, *ctx;
    cudaGetSymbolAddress((void**)&Qp,  g_Qp);
    cudaGetSymbolAddress((void**)&Kp,  g_Kp);
    cudaGetSymbolAddress((void**)&Vp,  g_Vp);
    cudaGetSymbolAddress((void**)&ctx, g_ctx);

    cudaFuncSetAttribute(attn_kernel, cudaFuncAttributeMaxDynamicSharedMemorySize, ATTN_SMEM);

    // fused QKV projection: one launch, 768 blocks
    sgemm_qkv_kernel<<<dim3(24, MROWS / 128), 256>>>(q, k, v, Wqkv, bqkv, Qp, Kp, Vp);

    // flash attention
    attn_kernel<<<dim3(S_LEN / 128, NHEAD, BATCH), 256, ATTN_SMEM>>>(Qp, Kp, Vp, mask, ctx);

    // output projection
    sgemm_out_kernel<<<dim3(E_DIM / 128, MROWS / 128), 256>>>(ctx, Wout, bout, out);
}

// round 15
// speedup vs baseline: 1.2589x; 1.2589x over previous
#include <cuda_runtime.h>

#define S_LEN 2048
#define E_DIM 1024
#define NHEAD 16
#define DHEAD 64
#define BATCH 2
#define MROWS 4096   // BATCH * S_LEN
#define KDIM  1024

// ---------------- scratch (allocation-free) ----------------
__device__ float g_Qp[BATCH * NHEAD * S_LEN * DHEAD];  // [b][h][s][d]
__device__ float g_Kp[BATCH * NHEAD * S_LEN * DHEAD];
__device__ float g_Vp[BATCH * NHEAD * S_LEN * DHEAD];
__device__ float g_ctx[BATCH * S_LEN * E_DIM];         // [b][s][e]

// =====================================================================
// Fused QKV projection GEMM (unchanged — known good).
// =====================================================================
__global__ __launch_bounds__(256, 2) void sgemm_qkv_kernel(
    const float* __restrict__ q, const float* __restrict__ k,
    const float* __restrict__ v, const float* __restrict__ W,
    const float* __restrict__ bias,
    float* __restrict__ Qp, float* __restrict__ Kp, float* __restrict__ Vp)
{
    __shared__ float sA[2][16 * 132];
    __shared__ float sB[2][16 * 128];

    const int tid = threadIdx.x;
    const int tx = tid & 15, ty = tid >> 4;
    const int m0 = blockIdx.y << 7;
    const int bx = blockIdx.x;
    const int slice = bx >> 3;
    const int n0 = bx << 7;
    const int ldw = 3 * E_DIM;

    const float* X  = (slice == 0) ? q : (slice == 1) ? k : v;
    float* out      = (slice == 0) ? Qp : (slice == 1) ? Kp : Vp;

    const int aR0 = tid >> 2,         aC0 = (tid & 3) << 2;
    const int aR1 = (tid + 256) >> 2, aC1 = aC0;
    const int bR0 = tid >> 5,         bC0 = (tid & 31) << 2;
    const int bR1 = bR0 + 8,          bC1 = bC0;

    float acc[8][8];
    #pragma unroll
    for (int i = 0; i < 8; i++)
        #pragma unroll
        for (int j = 0; j < 8; j++) acc[i][j] = 0.f;

    float4 ra0, ra1, rb0, rb1;
    ra0 = *reinterpret_cast<const float4*>(&X[(m0 + aR0) * KDIM + aC0]);
    ra1 = *reinterpret_cast<const float4*>(&X[(m0 + aR1) * KDIM + aC1]);
    rb0 = *reinterpret_cast<const float4*>(&W[bR0 * ldw + n0 + bC0]);
    rb1 = *reinterpret_cast<const float4*>(&W[bR1 * ldw + n0 + bC1]);
    {
        float* p0 = &sA[0][aC0 * 132 + aR0];
        p0[0] = ra0.x; p0[132] = ra0.y; p0[264] = ra0.z; p0[396] = ra0.w;
        float* p1 = &sA[0][aC1 * 132 + aR1];
        p1[0] = ra1.x; p1[132] = ra1.y; p1[264] = ra1.z; p1[396] = ra1.w;
        *reinterpret_cast<float4*>(&sB[0][bR0 * 128 + bC0]) = rb0;
        *reinterpret_cast<float4*>(&sB[0][bR1 * 128 + bC1]) = rb1;
    }
    __syncthreads();

    int buf = 0;
    const int NSTEPS = KDIM / 16;
    for (int s = 0; s < NSTEPS; s++) {
        if (s + 1 < NSTEPS) {
            const int kn = (s + 1) << 4;
            ra0 = *reinterpret_cast<const float4*>(&X[(m0 + aR0) * KDIM + kn + aC0]);
            ra1 = *reinterpret_cast<const float4*>(&X[(m0 + aR1) * KDIM + kn + aC1]);
            rb0 = *reinterpret_cast<const float4*>(&W[(kn + bR0) * ldw + n0 + bC0]);
            rb1 = *reinterpret_cast<const float4*>(&W[(kn + bR1) * ldw + n0 + bC1]);
        }
        const float* pa = &sA[buf][ty << 3];
        const float* pb = &sB[buf][tx << 3];
        #pragma unroll 8
        for (int kk = 0; kk < 16; kk++) {
            float4 a0 = *reinterpret_cast<const float4*>(&pa[kk * 132]);
            float4 a1 = *reinterpret_cast<const float4*>(&pa[kk * 132 + 4]);
            float4 b0 = *reinterpret_cast<const float4*>(&pb[kk * 128]);
            float4 b1 = *reinterpret_cast<const float4*>(&pb[kk * 128 + 4]);
            float av[8] = {a0.x, a0.y, a0.z, a0.w, a1.x, a1.y, a1.z, a1.w};
            float bv[8] = {b0.x, b0.y, b0.z, b0.w, b1.x, b1.y, b1.z, b1.w};
            #pragma unroll
            for (int i = 0; i < 8; i++)
                #pragma unroll
                for (int j = 0; j < 8; j++)
                    acc[i][j] = fmaf(av[i], bv[j], acc[i][j]);
        }
        if (s + 1 < NSTEPS) {
            const int nb = buf ^ 1;
            float* p0 = &sA[nb][aC0 * 132 + aR0];
            p0[0] = ra0.x; p0[132] = ra0.y; p0[264] = ra0.z; p0[396] = ra0.w;
            float* p1 = &sA[nb][aC1 * 132 + aR1];
            p1[0] = ra1.x; p1[132] = ra1.y; p1[264] = ra1.z; p1[396] = ra1.w;
            *reinterpret_cast<float4*>(&sB[nb][bR0 * 128 + bC0]) = rb0;
            *reinterpret_cast<float4*>(&sB[nb][bR1 * 128 + bC1]) = rb1;
        }
        __syncthreads();
        buf ^= 1;
    }

    #pragma unroll
    for (int i = 0; i < 8; i++) {
        const int m  = m0 + (ty << 3) + i;
        const int bb = m >> 11;
        const int sq = m & (S_LEN - 1);
        #pragma unroll
        for (int j = 0; j < 8; j++) {
            const int n = n0 + (tx << 3) + j;
            const float val = acc[i][j] + bias[n];
            const int ns = n - (slice << 10);
            const int hh = ns >> 6, dd = ns & 63;
            out[((bb * NHEAD + hh) * S_LEN + sq) * DHEAD + dd] = val;
        }
    }
}

// =====================================================================
// Output projection GEMM (unchanged — known good).
// =====================================================================
__global__ __launch_bounds__(256, 2) void sgemm_out_kernel(
    const float* __restrict__ X, const float* __restrict__ W,
    const float* __restrict__ bias, float* __restrict__ out)
{
    __shared__ float sA[2][16 * 132];
    __shared__ float sB[2][16 * 128];

    const int tid = threadIdx.x;
    const int tx = tid & 15, ty = tid >> 4;
    const int m0 = blockIdx.y << 7;
    const int n0 = blockIdx.x << 7;
    const int ldw = E_DIM;

    const int aR0 = tid >> 2,         aC0 = (tid & 3) << 2;
    const int aR1 = (tid + 256) >> 2, aC1 = aC0;
    const int bR0 = tid >> 5,         bC0 = (tid & 31) << 2;
    const int bR1 = bR0 + 8,          bC1 = bC0;

    float acc[8][8];
    #pragma unroll
    for (int i = 0; i < 8; i++)
        #pragma unroll
        for (int j = 0; j < 8; j++) acc[i][j] = 0.f;

    float4 ra0, ra1, rb0, rb1;
    ra0 = *reinterpret_cast<const float4*>(&X[(m0 + aR0) * KDIM + aC0]);
    ra1 = *reinterpret_cast<const float4*>(&X[(m0 + aR1) * KDIM + aC1]);
    rb0 = *reinterpret_cast<const float4*>(&W[bR0 * ldw + n0 + bC0]);
    rb1 = *reinterpret_cast<const float4*>(&W[bR1 * ldw + n0 + bC1]);
    {
        float* p0 = &sA[0][aC0 * 132 + aR0];
        p0[0] = ra0.x; p0[132] = ra0.y; p0[264] = ra0.z; p0[396] = ra0.w;
        float* p1 = &sA[0][aC1 * 132 + aR1];
        p1[0] = ra1.x; p1[132] = ra1.y; p1[264] = ra1.z; p1[396] = ra1.w;
        *reinterpret_cast<float4*>(&sB[0][bR0 * 128 + bC0]) = rb0;
        *reinterpret_cast<float4*>(&sB[0][bR1 * 128 + bC1]) = rb1;
    }
    __syncthreads();

    int buf = 0;
    const int NSTEPS = KDIM / 16;
    for (int s = 0; s < NSTEPS; s++) {
        if (s + 1 < NSTEPS) {
            const int kn = (s + 1) << 4;
            ra0 = *reinterpret_cast<const float4*>(&X[(m0 + aR0) * KDIM + kn + aC0]);
            ra1 = *reinterpret_cast<const float4*>(&X[(m0 + aR1) * KDIM + kn + aC1]);
            rb0 = *reinterpret_cast<const float4*>(&W[(kn + bR0) * ldw + n0 + bC0]);
            rb1 = *reinterpret_cast<const float4*>(&W[(kn + bR1) * ldw + n0 + bC1]);
        }
        const float* pa = &sA[buf][ty << 3];
        const float* pb = &sB[buf][tx << 3];
        #pragma unroll 8
        for (int kk = 0; kk < 16; kk++) {
            float4 a0 = *reinterpret_cast<const float4*>(&pa[kk * 132]);
            float4 a1 = *reinterpret_cast<const float4*>(&pa[kk * 132 + 4]);
            float4 b0 = *reinterpret_cast<const float4*>(&pb[kk * 128]);
            float4 b1 = *reinterpret_cast<const float4*>(&pb[kk * 128 + 4]);
            float av[8] = {a0.x, a0.y, a0.z, a0.w, a1.x, a1.y, a1.z, a1.w};
            float bv[8] = {b0.x, b0.y, b0.z, b0.w, b1.x, b1.y, b1.z, b1.w};
            #pragma unroll
            for (int i = 0; i < 8; i++)
                #pragma unroll
                for (int j = 0; j < 8; j++)
                    acc[i][j] = fmaf(av[i], bv[j], acc[i][j]);
        }
        if (s + 1 < NSTEPS) {
            const int nb = buf ^ 1;
            float* p0 = &sA[nb][aC0 * 132 + aR0];
            p0[0] = ra0.x; p0[132] = ra0.y; p0[264] = ra0.z; p0[396] = ra0.w;
            float* p1 = &sA[nb][aC1 * 132 + aR1];
            p1[0] = ra1.x; p1[132] = ra1.y; p1[264] = ra1.z; p1[396] = ra1.w;
            *reinterpret_cast<float4*>(&sB[nb][bR0 * 128 + bC0]) = rb0;
            *reinterpret_cast<float4*>(&sB[nb][bR1 * 128 + bC1]) = rb1;
        }
        __syncthreads();
        buf ^= 1;
    }

    #pragma unroll
    for (int i = 0; i < 8; i++) {
        const int m = m0 + (ty << 3) + i;
        #pragma unroll
        for (int j = 0; j < 8; j++) {
            const int n = n0 + (tx << 3) + j;
            out[m * E_DIM + n] = acc[i][j] + bias[n];
        }
    }
}

// =====================================================================
// tf32 mma.sync helpers
// =====================================================================
__device__ __forceinline__ unsigned f2tf(float x) {
    unsigned r;
    asm("cvt.rna.tf32.f32 %0, %1;" : "=r"(r) : "f"(x));
    return r;
}

__device__ __forceinline__ void mma8(float c[4], const unsigned a[4],
                                     unsigned b0, unsigned b1) {
    asm volatile(
        "mma.sync.aligned.m16n8k8.row.col.f32.tf32.tf32.f32 "
        "{%0,%1,%2,%3}, {%4,%5,%6,%7}, {%8,%9}, {%0,%1,%2,%3};"
        : "+f"(c[0]), "+f"(c[1]), "+f"(c[2]), "+f"(c[3])
        : "r"(a[0]), "r"(a[1]), "r"(a[2]), "r"(a[3]), "r"(b0), "r"(b1));
}

// C-fragment (rows g,g+8; cols 2t,2t+1 per lane) -> A-fragment
// (a0=P[g][t], a1=P[g+8][t], a2=P[g][t+4], a3=P[g+8][t+4]) via intra-quad shfl.
__device__ __forceinline__ void ptrans(const float c[4], unsigned pa[4],
                                       int src0, int src1, bool odd) {
    float v0 = __shfl_sync(0xffffffffu, c[0], src0);
    float v1 = __shfl_sync(0xffffffffu, c[1], src0);
    pa[0] = f2tf(odd ? v1 : v0);
    float v2 = __shfl_sync(0xffffffffu, c[2], src0);
    float v3 = __shfl_sync(0xffffffffu, c[3], src0);
    pa[1] = f2tf(odd ? v3 : v2);
    float u0 = __shfl_sync(0xffffffffu, c[0], src1);
    float u1 = __shfl_sync(0xffffffffu, c[1], src1);
    pa[2] = f2tf(odd ? u1 : u0);
    float u2 = __shfl_sync(0xffffffffu, c[2], src1);
    float u3 = __shfl_sync(0xffffffffu, c[3], src1);
    pa[3] = f2tf(odd ? u3 : u2);
}

// =====================================================================
// Flash attention on tf32 tensor cores.
// grid (16, 16, 2), 256 threads = 8 warps; warp w owns Q rows [16w,16w+16).
// Q A-frags register-resident.
// K staged as packed B-frags (k-dim = d; transpose inherent in Q@K^T):
//   Kz u32 addr = ((kcp*4 + tg)*64 + j)*4 + slot  holds K[j][16kcp+4slot+tg]
// V staged row-major tf32 bits, stride 72 (k-dim = j for P@V):
//   Vs[j*72 + d] = tf32(V[j][d]);  LDS.32 bank = (8t+g)&31 -> conflict-free
// =====================================================================
#define VSTR 72

__global__ __launch_bounds__(256, 2) void attn_kernel(
    const float* __restrict__ Qp, const float* __restrict__ Kp,
    const float* __restrict__ Vp, const int* __restrict__ mask,
    float* __restrict__ ctx)
{
    __shared__ unsigned Kz[4096];        // 16 KB
    __shared__ unsigned Vs[64 * VSTR];   // 18 KB

    const int tid  = threadIdx.x;
    const int lane = tid & 31;
    const int w    = tid >> 5;
    const int g    = lane >> 2;   // groupID (0..7)
    const int t    = lane & 3;    // thread-in-group (0..3)
    const int q0   = blockIdx.x << 7;
    const int h    = blockIdx.y, b = blockIdx.z;
    const int base = ((b * NHEAD + h) * S_LEN) * DHEAD;

    const int r0 = q0 + (w << 4) + g;      // this thread's even Q row
    // transpose shuffle sources (within 4-lane quad)
    const int src0 = (lane & 28) | (t >> 1);
    const int src1 = src0 + 2;
    const bool odd = (t & 1);

    // ---- Q fragments, register resident for the whole kernel ----
    unsigned qa[8][4];
    #pragma unroll
    for (int kc = 0; kc < 8; kc++) {
        qa[kc][0] = f2tf(Qp[base + r0 * DHEAD + kc * 8 + t]);
        qa[kc][1] = f2tf(Qp[base + (r0 + 8) * DHEAD + kc * 8 + t]);
        qa[kc][2] = f2tf(Qp[base + r0 * DHEAD + kc * 8 + t + 4]);
        qa[kc][3] = f2tf(Qp[base + (r0 + 8) * DHEAD + kc * 8 + t + 4]);
    }

    // ---- staging role constants ----
    const int sjlo  = lane >> 2;                     // j low 3 bits
    const int sslot = lane & 3;                      // K slot = f4 & 3
    const int skcp  = w & 3;                         // K kcp  = f4 >> 2
    const int sf4   = (lane & 3) + ((w & 3) << 2);   // d-float4 index 0..15
    const int swhi  = w >> 2;                        // high bit of j group

    float o[8][4];
    #pragma unroll
    for (int i = 0; i < 8; i++) { o[i][0] = o[i][1] = o[i][2] = o[i][3] = 0.f; }
    float m0 = -1e30f, m1 = -1e30f, l0 = 0.f, l1 = 0.f;

    for (int kt = 0; kt < S_LEN / 64; kt++) {
        const int k0 = kt << 6;
        __syncthreads();   // previous tile's readers done

        // ---- stage K (packed B-frag layout) and V (row-major, stride 72) ----
        #pragma unroll
        for (int i = 0; i < 4; i++) {
            const int j = sjlo + ((i * 2 + swhi) << 3);     // 0..63
            const int gaddr = base + (k0 + j) * DHEAD + (sf4 << 2);
            const int ab = skcp * 1024 + j * 4 + sslot;
            float4 kv = *reinterpret_cast<const float4*>(&Kp[gaddr]);
            Kz[ab]       = f2tf(kv.x);
            Kz[ab + 256] = f2tf(kv.y);
            Kz[ab + 512] = f2tf(kv.z);
            Kz[ab + 768] = f2tf(kv.w);
            float4 vv = *reinterpret_cast<const float4*>(&Vp[gaddr]);
            uint4 vz;
            vz.x = f2tf(vv.x); vz.y = f2tf(vv.y);
            vz.z = f2tf(vv.z); vz.w = f2tf(vv.w);
            *reinterpret_cast<uint4*>(&Vs[j * VSTR + (sf4 << 2)]) = vz;
        }
        __syncthreads();

        // ---- S = Q @ K^T ----
        float s[8][4];
        #pragma unroll
        for (int i = 0; i < 8; i++) { s[i][0] = s[i][1] = s[i][2] = s[i][3] = 0.f; }
        {
            const uint4* KzB = reinterpret_cast<const uint4*>(Kz);
            #pragma unroll
            for (int kcp = 0; kcp < 4; kcp++) {
                const uint4* row = &KzB[(kcp * 4 + t) * 64 + g];
                #pragma unroll
                for (int nt = 0; nt < 8; nt++) {
                    uint4 bb = row[nt * 8];
                    mma8(s[nt], qa[2 * kcp],     bb.x, bb.y);
                    mma8(s[nt], qa[2 * kcp + 1], bb.z, bb.w);
                }
            }
        }

        // ---- mask + scale (1/sqrt(64) = 0.125) ----
        #pragma unroll
        for (int nt = 0; nt < 8; nt++) {
            const int cb = k0 + nt * 8 + t * 2;
            const int2 mv0 = *reinterpret_cast<const int2*>(&mask[r0 * S_LEN + cb]);
            const int2 mv1 = *reinterpret_cast<const int2*>(&mask[(r0 + 8) * S_LEN + cb]);
            s[nt][0] = mv0.x ? s[nt][0] * 0.125f : -1e30f;
            s[nt][1] = mv0.y ? s[nt][1] * 0.125f : -1e30f;
            s[nt][2] = mv1.x ? s[nt][2] * 0.125f : -1e30f;
            s[nt][3] = mv1.y ? s[nt][3] * 0.125f : -1e30f;
        }

        // ---- online softmax (rows g and g+8; each row spread over 4 lanes) ----
        {
            float tm0 = -1e30f, tm1 = -1e30f;
            #pragma unroll
            for (int nt = 0; nt < 8; nt++) {
                tm0 = fmaxf(tm0, fmaxf(s[nt][0], s[nt][1]));
                tm1 = fmaxf(tm1, fmaxf(s[nt][2], s[nt][3]));
            }
            tm0 = fmaxf(tm0, __shfl_xor_sync(0xffffffffu, tm0, 1));
            tm0 = fmaxf(tm0, __shfl_xor_sync(0xffffffffu, tm0, 2));
            tm1 = fmaxf(tm1, __shfl_xor_sync(0xffffffffu, tm1, 1));
            tm1 = fmaxf(tm1, __shfl_xor_sync(0xffffffffu, tm1, 2));
            const float mn0 = fmaxf(m0, tm0), mn1 = fmaxf(m1, tm1);
            const float c0 = __expf(m0 - mn0), c1 = __expf(m1 - mn1);
            m0 = mn0; m1 = mn1;
            float ps0 = 0.f, ps1 = 0.f;
            #pragma unroll
            for (int nt = 0; nt < 8; nt++) {
                s[nt][0] = __expf(s[nt][0] - mn0);
                s[nt][1] = __expf(s[nt][1] - mn0);
                s[nt][2] = __expf(s[nt][2] - mn1);
                s[nt][3] = __expf(s[nt][3] - mn1);
                ps0 += s[nt][0] + s[nt][1];
                ps1 += s[nt][2] + s[nt][3];
            }
            ps0 += __shfl_xor_sync(0xffffffffu, ps0, 1);
            ps0 += __shfl_xor_sync(0xffffffffu, ps0, 2);
            ps1 += __shfl_xor_sync(0xffffffffu, ps1, 1);
            ps1 += __shfl_xor_sync(0xffffffffu, ps1, 2);
            l0 = l0 * c0 + ps0;
            l1 = l1 * c1 + ps1;
            #pragma unroll
            for (int nt = 0; nt < 8; nt++) {
                o[nt][0] *= c0; o[nt][1] *= c0;
                o[nt][2] *= c1; o[nt][3] *= c1;
            }
        }

        // ---- O += P @ V (P transposed in-register via shfl; B = V[j][d]) ----
        #pragma unroll
        for (int kcp = 0; kcp < 4; kcp++) {
            unsigned paA[4], paB[4];
            ptrans(s[2 * kcp],     paA, src0, src1, odd);   // j in [16kcp,   16kcp+8)
            ptrans(s[2 * kcp + 1], paB, src0, src1, odd);   // j in [16kcp+8, 16kcp+16)
            const unsigned* vr0 = &Vs[(16 * kcp + t) * VSTR + g];       // b0 row, chunk A
            const unsigned* vr1 = vr0 + 4 * VSTR;                        // b1 row, chunk A
            const unsigned* vr2 = vr0 + 8 * VSTR;                        // b0 row, chunk B
            const unsigned* vr3 = vr0 + 12 * VSTR;                       // b1 row, chunk B
            #pragma unroll
            for (int nt = 0; nt < 8; nt++) {
                const int d = nt * 8;
                mma8(o[nt], paA, vr0[d], vr1[d]);
                mma8(o[nt], paB, vr2[d], vr3[d]);
            }
        }
    }

    // ---- normalize + write ctx [b][s][e], e = h*64 + d ----
    const float inv0 = 1.f / l0, inv1 = 1.f / l1;
    float* c0p = &ctx[(b * S_LEN + r0) * E_DIM + h * DHEAD + t * 2];
    float* c1p = &ctx[(b * S_LEN + r0 + 8) * E_DIM + h * DHEAD + t * 2];
    #pragma unroll
    for (int nt = 0; nt < 8; nt++) {
        *reinterpret_cast<float2*>(&c0p[nt * 8]) =
            make_float2(o[nt][0] * inv0, o[nt][1] * inv0);
        *reinterpret_cast<float2*>(&c1p[nt * 8]) =
            make_float2(o[nt][2] * inv1, o[nt][3] * inv1);
    }
}

// =====================================================================
extern "C" void kernel_launch(void* const* d_in, const int* in_sizes, int n_in,
                              void* d_out, int out_size)
{
    const float* q    = (const float*)d_in[0];
    const float* k    = (const float*)d_in[1];
    const float* v    = (const float*)d_in[2];
    const int*   mask = (const int*)  d_in[3];
    const float* Wqkv = (const float*)d_in[4];
    const float* bqkv = (const float*)d_in[5];
    const float* Wout = (const float*)d_in[6];
    const float* bout = (const float*)d_in[7];
    float* out = (float*)d_out;
    (void)in_sizes; (void)n_in; (void)out_size;

    float *Qp, *Kp, *Vp, *ctx;
    cudaGetSymbolAddress((void**)&Qp,  g_Qp);
    cudaGetSymbolAddress((void**)&Kp,  g_Kp);
    cudaGetSymbolAddress((void**)&Vp,  g_Vp);
    cudaGetSymbolAddress((void**)&ctx, g_ctx);

    // fused QKV projection
    sgemm_qkv_kernel<<<dim3(24, MROWS / 128), 256>>>(q, k, v, Wqkv, bqkv, Qp, Kp, Vp);

    // flash attention (tf32 tensor cores)
    attn_kernel<<<dim3(S_LEN / 128, NHEAD, BATCH), 256>>>(Qp, Kp, Vp, mask, ctx);

    // output projection
    sgemm_out_kernel<<<dim3(E_DIM / 128, MROWS / 128), 256>>>(ctx, Wout, bout, out);
}

// round 16
// speedup vs baseline: 1.6946x; 1.3460x over previous
#include <cuda_runtime.h>

#define S_LEN 2048
#define E_DIM 1024
#define NHEAD 16
#define DHEAD 64
#define BATCH 2
#define MROWS 4096   // BATCH * S_LEN
#define KDIM  1024

// ---------------- scratch (allocation-free) ----------------
__device__ float g_Qp[BATCH * NHEAD * S_LEN * DHEAD];  // [b][h][s][d]
__device__ float g_Kp[BATCH * NHEAD * S_LEN * DHEAD];
__device__ float g_Vp[BATCH * NHEAD * S_LEN * DHEAD];
__device__ float g_ctx[BATCH * S_LEN * E_DIM];         // [b][s][e]

// =====================================================================
// tf32 mma helpers
// =====================================================================
__device__ __forceinline__ unsigned f2tf(float x) {
    unsigned r;
    asm("cvt.rna.tf32.f32 %0, %1;" : "=r"(r) : "f"(x));
    return r;
}

__device__ __forceinline__ void mma8(float c[4], const unsigned a[4],
                                     unsigned b0, unsigned b1) {
    asm volatile(
        "mma.sync.aligned.m16n8k8.row.col.f32.tf32.tf32.f32 "
        "{%0,%1,%2,%3}, {%4,%5,%6,%7}, {%8,%9}, {%0,%1,%2,%3};"
        : "+f"(c[0]), "+f"(c[1]), "+f"(c[2]), "+f"(c[3])
        : "r"(a[0]), "r"(a[1]), "r"(a[2]), "r"(a[3]), "r"(b0), "r"(b1));
}

// =====================================================================
// tf32 projection GEMM (2xTF32 activation split; W single tf32).
// Block 256 thr = 8 warps (4 m-warps x 2 n-warps); block tile 128x128;
// warp tile 32m x 64n; K staged 8 per double-buffered stage.
//   At2[k][m] (stride 132, uint2 = (hi,lo))  -> A frags: 4x LDS.64, CF
//   Wz [k][n] (stride 136, u32 tf32 bits)    -> B frags: 2x LDS.32, CF
// =====================================================================
#define ASTR 132
#define WSTR 136

struct ProjSmem {
    uint2    At2[2][8 * ASTR];
    unsigned Wz [2][8 * WSTR];
};

__device__ __forceinline__ void proj_stage_store(
    ProjSmem& sm, int b, int am, int ak4, int wk, int wn4,
    float4 xa, float4 wv)
{
    #pragma unroll
    for (int i = 0; i < 4; i++) {
        const float xv = (&xa.x)[i];
        const unsigned hb = f2tf(xv);
        const float hf = __uint_as_float(hb);
        const unsigned lb = f2tf(xv - hf);
        sm.At2[b][(ak4 + i) * ASTR + am] = make_uint2(hb, lb);
    }
    uint4 wz;
    wz.x = f2tf(wv.x); wz.y = f2tf(wv.y);
    wz.z = f2tf(wv.z); wz.w = f2tf(wv.w);
    *reinterpret_cast<uint4*>(&sm.Wz[b][wk * WSTR + (wn4 << 2)]) = wz;
}

__device__ __forceinline__ void proj_mainloop(
    ProjSmem& sm, float acc[2][8][4],
    const float* __restrict__ X, const float* __restrict__ W,
    int m0, int n0, int ldw,
    int am, int ak4, int wk, int wn4, int wm, int wn, int g, int t)
{
    // prologue: stage 0
    {
        float4 xa = *reinterpret_cast<const float4*>(&X[(m0 + am) * KDIM + ak4]);
        float4 wv = *reinterpret_cast<const float4*>(&W[wk * ldw + n0 + (wn4 << 2)]);
        proj_stage_store(sm, 0, am, ak4, wk, wn4, xa, wv);
    }
    __syncthreads();

    int buf = 0;
    const int NST = KDIM / 8;   // 128
    for (int s = 0; s < NST; s++) {
        float4 xa, wv;
        if (s + 1 < NST) {
            const int kn = (s + 1) << 3;
            xa = *reinterpret_cast<const float4*>(&X[(m0 + am) * KDIM + kn + ak4]);
            wv = *reinterpret_cast<const float4*>(&W[(kn + wk) * ldw + n0 + (wn4 << 2)]);
        }

        // ---- A fragments (hi+lo via 4x LDS.64 per mtile) ----
        unsigned aHi[2][4], aLo[2][4];
        #pragma unroll
        for (int mt = 0; mt < 2; mt++) {
            const int mb = wm * 32 + mt * 16 + g;
            uint2 p0 = sm.At2[buf][t * ASTR + mb];
            uint2 p1 = sm.At2[buf][t * ASTR + mb + 8];
            uint2 p2 = sm.At2[buf][(t + 4) * ASTR + mb];
            uint2 p3 = sm.At2[buf][(t + 4) * ASTR + mb + 8];
            aHi[mt][0] = p0.x; aHi[mt][1] = p1.x; aHi[mt][2] = p2.x; aHi[mt][3] = p3.x;
            aLo[mt][0] = p0.y; aLo[mt][1] = p1.y; aLo[mt][2] = p2.y; aLo[mt][3] = p3.y;
        }
        // ---- B fragments ----
        unsigned b0[8], b1[8];
        #pragma unroll
        for (int nt = 0; nt < 8; nt++) {
            const int nb = wn * 64 + nt * 8 + g;
            b0[nt] = sm.Wz[buf][t * WSTR + nb];
            b1[nt] = sm.Wz[buf][(t + 4) * WSTR + nb];
        }
        // ---- 32 mma ----
        #pragma unroll
        for (int mt = 0; mt < 2; mt++)
            #pragma unroll
            for (int nt = 0; nt < 8; nt++) {
                mma8(acc[mt][nt], aHi[mt], b0[nt], b1[nt]);
                mma8(acc[mt][nt], aLo[mt], b0[nt], b1[nt]);
            }

        if (s + 1 < NST)
            proj_stage_store(sm, buf ^ 1, am, ak4, wk, wn4, xa, wv);
        __syncthreads();
        buf ^= 1;
    }
}

// ---- fused QKV projection: grid (24, 32); head-split epilogue ----
__global__ __launch_bounds__(256, 2) void tf32_qkv_kernel(
    const float* __restrict__ q, const float* __restrict__ k,
    const float* __restrict__ v, const float* __restrict__ W,
    const float* __restrict__ bias,
    float* __restrict__ Qp, float* __restrict__ Kp, float* __restrict__ Vp)
{
    __shared__ ProjSmem sm;

    const int tid  = threadIdx.x;
    const int lane = tid & 31;
    const int w    = tid >> 5;
    const int g    = lane >> 2, t = lane & 3;
    const int wm   = w >> 1, wn = w & 1;
    const int m0   = blockIdx.y << 7;
    const int bx   = blockIdx.x;
    const int slice = bx >> 3;
    const int n0   = bx << 7;                    // global col in [0,3072)

    const float* X = (slice == 0) ? q : (slice == 1) ? k : v;
    float* out     = (slice == 0) ? Qp : (slice == 1) ? Kp : Vp;

    const int am = tid >> 1, ak4 = (tid & 1) << 2;   // A staging role
    const int wk = tid >> 5, wn4 = tid & 31;         // W staging role

    float acc[2][8][4];
    #pragma unroll
    for (int mt = 0; mt < 2; mt++)
        #pragma unroll
        for (int nt = 0; nt < 8; nt++)
            acc[mt][nt][0] = acc[mt][nt][1] = acc[mt][nt][2] = acc[mt][nt][3] = 0.f;

    proj_mainloop(sm, acc, X, W, m0, n0, 3 * E_DIM, am, ak4, wk, wn4, wm, wn, g, t);

    // epilogue: bias + head-split store [b][h][s][d]
    #pragma unroll
    for (int mt = 0; mt < 2; mt++) {
        const int row0 = m0 + wm * 32 + mt * 16 + g;
        #pragma unroll
        for (int nt = 0; nt < 8; nt++) {
            const int n  = n0 + wn * 64 + nt * 8 + 2 * t;
            const float2 bv = *reinterpret_cast<const float2*>(&bias[n]);
            const int ns = n - (slice << 10);
            const int hh = ns >> 6, dd = ns & 63;
            #pragma unroll
            for (int rr = 0; rr < 2; rr++) {
                const int m  = row0 + rr * 8;
                const int bb = m >> 11, sq = m & (S_LEN - 1);
                float2 val = make_float2(acc[mt][nt][2 * rr]     + bv.x,
                                         acc[mt][nt][2 * rr + 1] + bv.y);
                *reinterpret_cast<float2*>(
                    &out[((bb * NHEAD + hh) * S_LEN + sq) * DHEAD + dd]) = val;
            }
        }
    }
}

// ---- output projection: grid (8, 32); row-major epilogue ----
__global__ __launch_bounds__(256, 2) void tf32_out_kernel(
    const float* __restrict__ X, const float* __restrict__ W,
    const float* __restrict__ bias, float* __restrict__ out)
{
    __shared__ ProjSmem sm;

    const int tid  = threadIdx.x;
    const int lane = tid & 31;
    const int w    = tid >> 5;
    const int g    = lane >> 2, t = lane & 3;
    const int wm   = w >> 1, wn = w & 1;
    const int m0   = blockIdx.y << 7;
    const int n0   = blockIdx.x << 7;

    const int am = tid >> 1, ak4 = (tid & 1) << 2;
    const int wk = tid >> 5, wn4 = tid & 31;

    float acc[2][8][4];
    #pragma unroll
    for (int mt = 0; mt < 2; mt++)
        #pragma unroll
        for (int nt = 0; nt < 8; nt++)
            acc[mt][nt][0] = acc[mt][nt][1] = acc[mt][nt][2] = acc[mt][nt][3] = 0.f;

    proj_mainloop(sm, acc, X, W, m0, n0, E_DIM, am, ak4, wk, wn4, wm, wn, g, t);

    #pragma unroll
    for (int mt = 0; mt < 2; mt++) {
        const int row0 = m0 + wm * 32 + mt * 16 + g;
        #pragma unroll
        for (int nt = 0; nt < 8; nt++) {
            const int n = n0 + wn * 64 + nt * 8 + 2 * t;
            const float2 bv = *reinterpret_cast<const float2*>(&bias[n]);
            #pragma unroll
            for (int rr = 0; rr < 2; rr++) {
                const int m = row0 + rr * 8;
                float2 val = make_float2(acc[mt][nt][2 * rr]     + bv.x,
                                         acc[mt][nt][2 * rr + 1] + bv.y);
                *reinterpret_cast<float2*>(&out[m * E_DIM + n]) = val;
            }
        }
    }
}

// C-fragment (rows g,g+8; cols 2t,2t+1 per lane) -> A-fragment via quad shfl.
__device__ __forceinline__ void ptrans(const float c[4], unsigned pa[4],
                                       int src0, int src1, bool odd) {
    float v0 = __shfl_sync(0xffffffffu, c[0], src0);
    float v1 = __shfl_sync(0xffffffffu, c[1], src0);
    pa[0] = f2tf(odd ? v1 : v0);
    float v2 = __shfl_sync(0xffffffffu, c[2], src0);
    float v3 = __shfl_sync(0xffffffffu, c[3], src0);
    pa[1] = f2tf(odd ? v3 : v2);
    float u0 = __shfl_sync(0xffffffffu, c[0], src1);
    float u1 = __shfl_sync(0xffffffffu, c[1], src1);
    pa[2] = f2tf(odd ? u1 : u0);
    float u2 = __shfl_sync(0xffffffffu, c[2], src1);
    float u3 = __shfl_sync(0xffffffffu, c[3], src1);
    pa[3] = f2tf(odd ? u3 : u2);
}

// =====================================================================
// Flash attention on tf32 tensor cores (unchanged from R15 — passing).
// =====================================================================
#define VSTR 72

__global__ __launch_bounds__(256, 2) void attn_kernel(
    const float* __restrict__ Qp, const float* __restrict__ Kp,
    const float* __restrict__ Vp, const int* __restrict__ mask,
    float* __restrict__ ctx)
{
    __shared__ unsigned Kz[4096];        // 16 KB
    __shared__ unsigned Vs[64 * VSTR];   // 18 KB

    const int tid  = threadIdx.x;
    const int lane = tid & 31;
    const int w    = tid >> 5;
    const int g    = lane >> 2;
    const int t    = lane & 3;
    const int q0   = blockIdx.x << 7;
    const int h    = blockIdx.y, b = blockIdx.z;
    const int base = ((b * NHEAD + h) * S_LEN) * DHEAD;

    const int r0 = q0 + (w << 4) + g;
    const int src0 = (lane & 28) | (t >> 1);
    const int src1 = src0 + 2;
    const bool odd = (t & 1);

    unsigned qa[8][4];
    #pragma unroll
    for (int kc = 0; kc < 8; kc++) {
        qa[kc][0] = f2tf(Qp[base + r0 * DHEAD + kc * 8 + t]);
        qa[kc][1] = f2tf(Qp[base + (r0 + 8) * DHEAD + kc * 8 + t]);
        qa[kc][2] = f2tf(Qp[base + r0 * DHEAD + kc * 8 + t + 4]);
        qa[kc][3] = f2tf(Qp[base + (r0 + 8) * DHEAD + kc * 8 + t + 4]);
    }

    const int sjlo  = lane >> 2;
    const int sslot = lane & 3;
    const int skcp  = w & 3;
    const int sf4   = (lane & 3) + ((w & 3) << 2);
    const int swhi  = w >> 2;

    float o[8][4];
    #pragma unroll
    for (int i = 0; i < 8; i++) { o[i][0] = o[i][1] = o[i][2] = o[i][3] = 0.f; }
    float m0 = -1e30f, m1 = -1e30f, l0 = 0.f, l1 = 0.f;

    for (int kt = 0; kt < S_LEN / 64; kt++) {
        const int k0 = kt << 6;
        __syncthreads();

        #pragma unroll
        for (int i = 0; i < 4; i++) {
            const int j = sjlo + ((i * 2 + swhi) << 3);
            const int gaddr = base + (k0 + j) * DHEAD + (sf4 << 2);
            const int ab = skcp * 1024 + j * 4 + sslot;
            float4 kv = *reinterpret_cast<const float4*>(&Kp[gaddr]);
            Kz[ab]       = f2tf(kv.x);
            Kz[ab + 256] = f2tf(kv.y);
            Kz[ab + 512] = f2tf(kv.z);
            Kz[ab + 768] = f2tf(kv.w);
            float4 vv = *reinterpret_cast<const float4*>(&Vp[gaddr]);
            uint4 vz;
            vz.x = f2tf(vv.x); vz.y = f2tf(vv.y);
            vz.z = f2tf(vv.z); vz.w = f2tf(vv.w);
            *reinterpret_cast<uint4*>(&Vs[j * VSTR + (sf4 << 2)]) = vz;
        }
        __syncthreads();

        float s[8][4];
        #pragma unroll
        for (int i = 0; i < 8; i++) { s[i][0] = s[i][1] = s[i][2] = s[i][3] = 0.f; }
        {
            const uint4* KzB = reinterpret_cast<const uint4*>(Kz);
            #pragma unroll
            for (int kcp = 0; kcp < 4; kcp++) {
                const uint4* row = &KzB[(kcp * 4 + t) * 64 + g];
                #pragma unroll
                for (int nt = 0; nt < 8; nt++) {
                    uint4 bb = row[nt * 8];
                    mma8(s[nt], qa[2 * kcp],     bb.x, bb.y);
                    mma8(s[nt], qa[2 * kcp + 1], bb.z, bb.w);
                }
            }
        }

        #pragma unroll
        for (int nt = 0; nt < 8; nt++) {
            const int cb = k0 + nt * 8 + t * 2;
            const int2 mv0 = *reinterpret_cast<const int2*>(&mask[r0 * S_LEN + cb]);
            const int2 mv1 = *reinterpret_cast<const int2*>(&mask[(r0 + 8) * S_LEN + cb]);
            s[nt][0] = mv0.x ? s[nt][0] * 0.125f : -1e30f;
            s[nt][1] = mv0.y ? s[nt][1] * 0.125f : -1e30f;
            s[nt][2] = mv1.x ? s[nt][2] * 0.125f : -1e30f;
            s[nt][3] = mv1.y ? s[nt][3] * 0.125f : -1e30f;
        }

        {
            float tm0 = -1e30f, tm1 = -1e30f;
            #pragma unroll
            for (int nt = 0; nt < 8; nt++) {
                tm0 = fmaxf(tm0, fmaxf(s[nt][0], s[nt][1]));
                tm1 = fmaxf(tm1, fmaxf(s[nt][2], s[nt][3]));
            }
            tm0 = fmaxf(tm0, __shfl_xor_sync(0xffffffffu, tm0, 1));
            tm0 = fmaxf(tm0, __shfl_xor_sync(0xffffffffu, tm0, 2));
            tm1 = fmaxf(tm1, __shfl_xor_sync(0xffffffffu, tm1, 1));
            tm1 = fmaxf(tm1, __shfl_xor_sync(0xffffffffu, tm1, 2));
            const float mn0 = fmaxf(m0, tm0), mn1 = fmaxf(m1, tm1);
            const float c0 = __expf(m0 - mn0), c1 = __expf(m1 - mn1);
            m0 = mn0; m1 = mn1;
            float ps0 = 0.f, ps1 = 0.f;
            #pragma unroll
            for (int nt = 0; nt < 8; nt++) {
                s[nt][0] = __expf(s[nt][0] - mn0);
                s[nt][1] = __expf(s[nt][1] - mn0);
                s[nt][2] = __expf(s[nt][2] - mn1);
                s[nt][3] = __expf(s[nt][3] - mn1);
                ps0 += s[nt][0] + s[nt][1];
                ps1 += s[nt][2] + s[nt][3];
            }
            ps0 += __shfl_xor_sync(0xffffffffu, ps0, 1);
            ps0 += __shfl_xor_sync(0xffffffffu, ps0, 2);
            ps1 += __shfl_xor_sync(0xffffffffu, ps1, 1);
            ps1 += __shfl_xor_sync(0xffffffffu, ps1, 2);
            l0 = l0 * c0 + ps0;
            l1 = l1 * c1 + ps1;
            #pragma unroll
            for (int nt = 0; nt < 8; nt++) {
                o[nt][0] *= c0; o[nt][1] *= c0;
                o[nt][2] *= c1; o[nt][3] *= c1;
            }
        }

        #pragma unroll
        for (int kcp = 0; kcp < 4; kcp++) {
            unsigned paA[4], paB[4];
            ptrans(s[2 * kcp],     paA, src0, src1, odd);
            ptrans(s[2 * kcp + 1], paB, src0, src1, odd);
            const unsigned* vr0 = &Vs[(16 * kcp + t) * VSTR + g];
            const unsigned* vr1 = vr0 + 4 * VSTR;
            const unsigned* vr2 = vr0 + 8 * VSTR;
            const unsigned* vr3 = vr0 + 12 * VSTR;
            #pragma unroll
            for (int nt = 0; nt < 8; nt++) {
                const int d = nt * 8;
                mma8(o[nt], paA, vr0[d], vr1[d]);
                mma8(o[nt], paB, vr2[d], vr3[d]);
            }
        }
    }

    const float inv0 = 1.f / l0, inv1 = 1.f / l1;
    float* c0p = &ctx[(b * S_LEN + r0) * E_DIM + h * DHEAD + t * 2];
    float* c1p = &ctx[(b * S_LEN + r0 + 8) * E_DIM + h * DHEAD + t * 2];
    #pragma unroll
    for (int nt = 0; nt < 8; nt++) {
        *reinterpret_cast<float2*>(&c0p[nt * 8]) =
            make_float2(o[nt][0] * inv0, o[nt][1] * inv0);
        *reinterpret_cast<float2*>(&c1p[nt * 8]) =
            make_float2(o[nt][2] * inv1, o[nt][3] * inv1);
    }
}

// =====================================================================
extern "C" void kernel_launch(void* const* d_in, const int* in_sizes, int n_in,
                              void* d_out, int out_size)
{
    const float* q    = (const float*)d_in[0];
    const float* k    = (const float*)d_in[1];
    const float* v    = (const float*)d_in[2];
    const int*   mask = (const int*)  d_in[3];
    const float* Wqkv = (const float*)d_in[4];
    const float* bqkv = (const float*)d_in[5];
    const float* Wout = (const float*)d_in[6];
    const float* bout = (const float*)d_in[7];
    float* out = (float*)d_out;
    (void)in_sizes; (void)n_in; (void)out_size;

    float *Qp, *Kp, *Vp, *ctx;
    cudaGetSymbolAddress((void**)&Qp,  g_Qp);
    cudaGetSymbolAddress((void**)&Kp,  g_Kp);
    cudaGetSymbolAddress((void**)&Vp,  g_Vp);
    cudaGetSymbolAddress((void**)&ctx, g_ctx);

    // fused QKV projection (tf32 tensor cores, 2xTF32 A-split)
    tf32_qkv_kernel<<<dim3(24, MROWS / 128), 256>>>(q, k, v, Wqkv, bqkv, Qp, Kp, Vp);

    // flash attention (tf32 tensor cores)
    attn_kernel<<<dim3(S_LEN / 128, NHEAD, BATCH), 256>>>(Qp, Kp, Vp, mask, ctx);

    // output projection (tf32 tensor cores)
    tf32_out_kernel<<<dim3(E_DIM / 128, MROWS / 128), 256>>>(ctx, Wout, bout, out);
}

// round 17
// speedup vs baseline: 1.7676x; 1.0431x over previous
#include <cuda_runtime.h>
#include <cuda_fp16.h>

#define S_LEN 2048
#define E_DIM 1024
#define NHEAD 16
#define DHEAD 64
#define BATCH 2
#define MROWS 4096   // BATCH * S_LEN
#define KDIM  1024

// ---------------- scratch (allocation-free) ----------------
__device__ float g_Qp[BATCH * NHEAD * S_LEN * DHEAD];  // [b][h][s][d]
__device__ float g_Kp[BATCH * NHEAD * S_LEN * DHEAD];
__device__ float g_Vp[BATCH * NHEAD * S_LEN * DHEAD];
__device__ float g_ctx[BATCH * S_LEN * E_DIM];         // [b][s][e]

// =====================================================================
// mma helpers
// =====================================================================
__device__ __forceinline__ unsigned f2tf(float x) {
    unsigned r;
    asm("cvt.rna.tf32.f32 %0, %1;" : "=r"(r) : "f"(x));
    return r;
}

__device__ __forceinline__ void mma8(float c[4], const unsigned a[4],
                                     unsigned b0, unsigned b1) {
    asm volatile(
        "mma.sync.aligned.m16n8k8.row.col.f32.tf32.tf32.f32 "
        "{%0,%1,%2,%3}, {%4,%5,%6,%7}, {%8,%9}, {%0,%1,%2,%3};"
        : "+f"(c[0]), "+f"(c[1]), "+f"(c[2]), "+f"(c[3])
        : "r"(a[0]), "r"(a[1]), "r"(a[2]), "r"(a[3]), "r"(b0), "r"(b1));
}

__device__ __forceinline__ void mma16(float c[4], const unsigned a[4],
                                      unsigned b0, unsigned b1) {
    asm volatile(
        "mma.sync.aligned.m16n8k16.row.col.f32.f16.f16.f32 "
        "{%0,%1,%2,%3}, {%4,%5,%6,%7}, {%8,%9}, {%0,%1,%2,%3};"
        : "+f"(c[0]), "+f"(c[1]), "+f"(c[2]), "+f"(c[3])
        : "r"(a[0]), "r"(a[1]), "r"(a[2]), "r"(a[3]), "r"(b0), "r"(b1));
}

// pack16(lo, hi): fp16x2 with low half = lo, high half = hi
__device__ __forceinline__ unsigned pack16(float lo, float hi) {
    unsigned r;
    asm("cvt.rn.f16x2.f32 %0, %1, %2;" : "=r"(r) : "f"(hi), "f"(lo));
    return r;
}

// =====================================================================
// tf32 projection GEMM (2xTF32 activation split; W single tf32).
// Unchanged from R16 — known good (347us QKV / ~115us out-proj).
// =====================================================================
#define ASTR 132
#define WSTR 136

struct ProjSmem {
    uint2    At2[2][8 * ASTR];
    unsigned Wz [2][8 * WSTR];
};

__device__ __forceinline__ void proj_stage_store(
    ProjSmem& sm, int b, int am, int ak4, int wk, int wn4,
    float4 xa, float4 wv)
{
    #pragma unroll
    for (int i = 0; i < 4; i++) {
        const float xv = (&xa.x)[i];
        const unsigned hb = f2tf(xv);
        const float hf = __uint_as_float(hb);
        const unsigned lb = f2tf(xv - hf);
        sm.At2[b][(ak4 + i) * ASTR + am] = make_uint2(hb, lb);
    }
    uint4 wz;
    wz.x = f2tf(wv.x); wz.y = f2tf(wv.y);
    wz.z = f2tf(wv.z); wz.w = f2tf(wv.w);
    *reinterpret_cast<uint4*>(&sm.Wz[b][wk * WSTR + (wn4 << 2)]) = wz;
}

__device__ __forceinline__ void proj_mainloop(
    ProjSmem& sm, float acc[2][8][4],
    const float* __restrict__ X, const float* __restrict__ W,
    int m0, int n0, int ldw,
    int am, int ak4, int wk, int wn4, int wm, int wn, int g, int t)
{
    {
        float4 xa = *reinterpret_cast<const float4*>(&X[(m0 + am) * KDIM + ak4]);
        float4 wv = *reinterpret_cast<const float4*>(&W[wk * ldw + n0 + (wn4 << 2)]);
        proj_stage_store(sm, 0, am, ak4, wk, wn4, xa, wv);
    }
    __syncthreads();

    int buf = 0;
    const int NST = KDIM / 8;   // 128
    for (int s = 0; s < NST; s++) {
        float4 xa, wv;
        if (s + 1 < NST) {
            const int kn = (s + 1) << 3;
            xa = *reinterpret_cast<const float4*>(&X[(m0 + am) * KDIM + kn + ak4]);
            wv = *reinterpret_cast<const float4*>(&W[(kn + wk) * ldw + n0 + (wn4 << 2)]);
        }

        unsigned aHi[2][4], aLo[2][4];
        #pragma unroll
        for (int mt = 0; mt < 2; mt++) {
            const int mb = wm * 32 + mt * 16 + g;
            uint2 p0 = sm.At2[buf][t * ASTR + mb];
            uint2 p1 = sm.At2[buf][t * ASTR + mb + 8];
            uint2 p2 = sm.At2[buf][(t + 4) * ASTR + mb];
            uint2 p3 = sm.At2[buf][(t + 4) * ASTR + mb + 8];
            aHi[mt][0] = p0.x; aHi[mt][1] = p1.x; aHi[mt][2] = p2.x; aHi[mt][3] = p3.x;
            aLo[mt][0] = p0.y; aLo[mt][1] = p1.y; aLo[mt][2] = p2.y; aLo[mt][3] = p3.y;
        }
        unsigned b0[8], b1[8];
        #pragma unroll
        for (int nt = 0; nt < 8; nt++) {
            const int nb = wn * 64 + nt * 8 + g;
            b0[nt] = sm.Wz[buf][t * WSTR + nb];
            b1[nt] = sm.Wz[buf][(t + 4) * WSTR + nb];
        }
        #pragma unroll
        for (int mt = 0; mt < 2; mt++)
            #pragma unroll
            for (int nt = 0; nt < 8; nt++) {
                mma8(acc[mt][nt], aHi[mt], b0[nt], b1[nt]);
                mma8(acc[mt][nt], aLo[mt], b0[nt], b1[nt]);
            }

        if (s + 1 < NST)
            proj_stage_store(sm, buf ^ 1, am, ak4, wk, wn4, xa, wv);
        __syncthreads();
        buf ^= 1;
    }
}

// ---- fused QKV projection: grid (24, 32); head-split epilogue ----
__global__ __launch_bounds__(256, 2) void tf32_qkv_kernel(
    const float* __restrict__ q, const float* __restrict__ k,
    const float* __restrict__ v, const float* __restrict__ W,
    const float* __restrict__ bias,
    float* __restrict__ Qp, float* __restrict__ Kp, float* __restrict__ Vp)
{
    __shared__ ProjSmem sm;

    const int tid  = threadIdx.x;
    const int lane = tid & 31;
    const int w    = tid >> 5;
    const int g    = lane >> 2, t = lane & 3;
    const int wm   = w >> 1, wn = w & 1;
    const int m0   = blockIdx.y << 7;
    const int bx   = blockIdx.x;
    const int slice = bx >> 3;
    const int n0   = bx << 7;

    const float* X = (slice == 0) ? q : (slice == 1) ? k : v;
    float* out     = (slice == 0) ? Qp : (slice == 1) ? Kp : Vp;

    const int am = tid >> 1, ak4 = (tid & 1) << 2;
    const int wk = tid >> 5, wn4 = tid & 31;

    float acc[2][8][4];
    #pragma unroll
    for (int mt = 0; mt < 2; mt++)
        #pragma unroll
        for (int nt = 0; nt < 8; nt++)
            acc[mt][nt][0] = acc[mt][nt][1] = acc[mt][nt][2] = acc[mt][nt][3] = 0.f;

    proj_mainloop(sm, acc, X, W, m0, n0, 3 * E_DIM, am, ak4, wk, wn4, wm, wn, g, t);

    #pragma unroll
    for (int mt = 0; mt < 2; mt++) {
        const int row0 = m0 + wm * 32 + mt * 16 + g;
        #pragma unroll
        for (int nt = 0; nt < 8; nt++) {
            const int n  = n0 + wn * 64 + nt * 8 + 2 * t;
            const float2 bv = *reinterpret_cast<const float2*>(&bias[n]);
            const int ns = n - (slice << 10);
            const int hh = ns >> 6, dd = ns & 63;
            #pragma unroll
            for (int rr = 0; rr < 2; rr++) {
                const int m  = row0 + rr * 8;
                const int bb = m >> 11, sq = m & (S_LEN - 1);
                float2 val = make_float2(acc[mt][nt][2 * rr]     + bv.x,
                                         acc[mt][nt][2 * rr + 1] + bv.y);
                *reinterpret_cast<float2*>(
                    &out[((bb * NHEAD + hh) * S_LEN + sq) * DHEAD + dd]) = val;
            }
        }
    }
}

// ---- output projection: grid (8, 32); row-major epilogue ----
__global__ __launch_bounds__(256, 2) void tf32_out_kernel(
    const float* __restrict__ X, const float* __restrict__ W,
    const float* __restrict__ bias, float* __restrict__ out)
{
    __shared__ ProjSmem sm;

    const int tid  = threadIdx.x;
    const int lane = tid & 31;
    const int w    = tid >> 5;
    const int g    = lane >> 2, t = lane & 3;
    const int wm   = w >> 1, wn = w & 1;
    const int m0   = blockIdx.y << 7;
    const int n0   = blockIdx.x << 7;

    const int am = tid >> 1, ak4 = (tid & 1) << 2;
    const int wk = tid >> 5, wn4 = tid & 31;

    float acc[2][8][4];
    #pragma unroll
    for (int mt = 0; mt < 2; mt++)
        #pragma unroll
        for (int nt = 0; nt < 8; nt++)
            acc[mt][nt][0] = acc[mt][nt][1] = acc[mt][nt][2] = acc[mt][nt][3] = 0.f;

    proj_mainloop(sm, acc, X, W, m0, n0, E_DIM, am, ak4, wk, wn4, wm, wn, g, t);

    #pragma unroll
    for (int mt = 0; mt < 2; mt++) {
        const int row0 = m0 + wm * 32 + mt * 16 + g;
        #pragma unroll
        for (int nt = 0; nt < 8; nt++) {
            const int n = n0 + wn * 64 + nt * 8 + 2 * t;
            const float2 bv = *reinterpret_cast<const float2*>(&bias[n]);
            #pragma unroll
            for (int rr = 0; rr < 2; rr++) {
                const int m = row0 + rr * 8;
                float2 val = make_float2(acc[mt][nt][2 * rr]     + bv.x,
                                         acc[mt][nt][2 * rr + 1] + bv.y);
                *reinterpret_cast<float2*>(&out[m * E_DIM + n]) = val;
            }
        }
    }
}

// =====================================================================
// Flash attention: QK on tf32 mma (unchanged), PV on fp16 m16n8k16.
// grid (16, 16, 2), 256 threads = 8 warps; warp w owns Q rows [16w,16w+16).
// K staged as packed tf32 B-frags (as R15/R16 — verified).
// V staged as fp16 j-pairs, transposed, stride 36 u32:
//   Vt[d*36 + jp] = f16x2(lo=V[2jp][d], hi=V[2jp+1][d])
//   consumer LDS.32 bank = (4g + t + 8kc) mod 32  -> bijection, CF
// P -> fp16 A-frags with ZERO shuffles (C-frag == A-frag identity):
//   a0=pack(s[2kc][0],s[2kc][1]), a1=pack(s[2kc][2],s[2kc][3]),
//   a2,a3 = same from s[2kc+1].
// =====================================================================
#define VTSTR 36

__global__ __launch_bounds__(256, 2) void attn_kernel(
    const float* __restrict__ Qp, const float* __restrict__ Kp,
    const float* __restrict__ Vp, const int* __restrict__ mask,
    float* __restrict__ ctx)
{
    __shared__ unsigned Kz[4096];          // 16 KB (tf32 K B-frags)
    __shared__ unsigned Vt[64 * VTSTR];    // 9 KB  (fp16x2 V, transposed pairs)

    const int tid  = threadIdx.x;
    const int lane = tid & 31;
    const int w    = tid >> 5;
    const int g    = lane >> 2;
    const int t    = lane & 3;
    const int q0   = blockIdx.x << 7;
    const int h    = blockIdx.y, b = blockIdx.z;
    const int base = ((b * NHEAD + h) * S_LEN) * DHEAD;

    const int r0 = q0 + (w << 4) + g;

    // ---- Q fragments, register resident ----
    unsigned qa[8][4];
    #pragma unroll
    for (int kc = 0; kc < 8; kc++) {
        qa[kc][0] = f2tf(Qp[base + r0 * DHEAD + kc * 8 + t]);
        qa[kc][1] = f2tf(Qp[base + (r0 + 8) * DHEAD + kc * 8 + t]);
        qa[kc][2] = f2tf(Qp[base + r0 * DHEAD + kc * 8 + t + 4]);
        qa[kc][3] = f2tf(Qp[base + (r0 + 8) * DHEAD + kc * 8 + t + 4]);
    }

    // ---- K staging role constants (unchanged layout) ----
    const int sjlo  = lane >> 2;
    const int sslot = lane & 3;
    const int skcp  = w & 3;
    const int sf4   = (lane & 3) + ((w & 3) << 2);
    const int swhi  = w >> 2;

    float o[8][4];
    #pragma unroll
    for (int i = 0; i < 8; i++) { o[i][0] = o[i][1] = o[i][2] = o[i][3] = 0.f; }
    float m0 = -1e30f, m1 = -1e30f, l0 = 0.f, l1 = 0.f;

    for (int kt = 0; kt < S_LEN / 64; kt++) {
        const int k0 = kt << 6;
        __syncthreads();   // previous tile's readers done

        // ---- stage K (packed tf32 B-frag layout) ----
        #pragma unroll
        for (int i = 0; i < 4; i++) {
            const int j = sjlo + ((i * 2 + swhi) << 3);
            const int gaddr = base + (k0 + j) * DHEAD + (sf4 << 2);
            const int ab = skcp * 1024 + j * 4 + sslot;
            float4 kv = *reinterpret_cast<const float4*>(&Kp[gaddr]);
            Kz[ab]       = f2tf(kv.x);
            Kz[ab + 256] = f2tf(kv.y);
            Kz[ab + 512] = f2tf(kv.z);
            Kz[ab + 768] = f2tf(kv.w);
        }
        // ---- stage V (fp16 pairs, transposed; warp w covers d rows 4w..4w+3, +32) ----
        #pragma unroll
        for (int p = 0; p < 2; p++) {
            const int d0 = 4 * w + 32 * p;
            const float4 v0 = *reinterpret_cast<const float4*>(
                &Vp[base + (k0 + 2 * lane) * DHEAD + d0]);
            const float4 v1 = *reinterpret_cast<const float4*>(
                &Vp[base + (k0 + 2 * lane + 1) * DHEAD + d0]);
            Vt[(d0 + 0) * VTSTR + lane] = pack16(v0.x, v1.x);
            Vt[(d0 + 1) * VTSTR + lane] = pack16(v0.y, v1.y);
            Vt[(d0 + 2) * VTSTR + lane] = pack16(v0.z, v1.z);
            Vt[(d0 + 3) * VTSTR + lane] = pack16(v0.w, v1.w);
        }
        __syncthreads();

        // ---- S = Q @ K^T (tf32) ----
        float s[8][4];
        #pragma unroll
        for (int i = 0; i < 8; i++) { s[i][0] = s[i][1] = s[i][2] = s[i][3] = 0.f; }
        {
            const uint4* KzB = reinterpret_cast<const uint4*>(Kz);
            #pragma unroll
            for (int kcp = 0; kcp < 4; kcp++) {
                const uint4* row = &KzB[(kcp * 4 + t) * 64 + g];
                #pragma unroll
                for (int nt = 0; nt < 8; nt++) {
                    uint4 bb = row[nt * 8];
                    mma8(s[nt], qa[2 * kcp],     bb.x, bb.y);
                    mma8(s[nt], qa[2 * kcp + 1], bb.z, bb.w);
                }
            }
        }

        // ---- mask + scale (1/sqrt(64) = 0.125) ----
        #pragma unroll
        for (int nt = 0; nt < 8; nt++) {
            const int cb = k0 + nt * 8 + t * 2;
            const int2 mv0 = *reinterpret_cast<const int2*>(&mask[r0 * S_LEN + cb]);
            const int2 mv1 = *reinterpret_cast<const int2*>(&mask[(r0 + 8) * S_LEN + cb]);
            s[nt][0] = mv0.x ? s[nt][0] * 0.125f : -1e30f;
            s[nt][1] = mv0.y ? s[nt][1] * 0.125f : -1e30f;
            s[nt][2] = mv1.x ? s[nt][2] * 0.125f : -1e30f;
            s[nt][3] = mv1.y ? s[nt][3] * 0.125f : -1e30f;
        }

        // ---- online softmax ----
        {
            float tm0 = -1e30f, tm1 = -1e30f;
            #pragma unroll
            for (int nt = 0; nt < 8; nt++) {
                tm0 = fmaxf(tm0, fmaxf(s[nt][0], s[nt][1]));
                tm1 = fmaxf(tm1, fmaxf(s[nt][2], s[nt][3]));
            }
            tm0 = fmaxf(tm0, __shfl_xor_sync(0xffffffffu, tm0, 1));
            tm0 = fmaxf(tm0, __shfl_xor_sync(0xffffffffu, tm0, 2));
            tm1 = fmaxf(tm1, __shfl_xor_sync(0xffffffffu, tm1, 1));
            tm1 = fmaxf(tm1, __shfl_xor_sync(0xffffffffu, tm1, 2));
            const float mn0 = fmaxf(m0, tm0), mn1 = fmaxf(m1, tm1);
            const float c0 = __expf(m0 - mn0), c1 = __expf(m1 - mn1);
            m0 = mn0; m1 = mn1;
            float ps0 = 0.f, ps1 = 0.f;
            #pragma unroll
            for (int nt = 0; nt < 8; nt++) {
                s[nt][0] = __expf(s[nt][0] - mn0);
                s[nt][1] = __expf(s[nt][1] - mn0);
                s[nt][2] = __expf(s[nt][2] - mn1);
                s[nt][3] = __expf(s[nt][3] - mn1);
                ps0 += s[nt][0] + s[nt][1];
                ps1 += s[nt][2] + s[nt][3];
            }
            ps0 += __shfl_xor_sync(0xffffffffu, ps0, 1);
            ps0 += __shfl_xor_sync(0xffffffffu, ps0, 2);
            ps1 += __shfl_xor_sync(0xffffffffu, ps1, 1);
            ps1 += __shfl_xor_sync(0xffffffffu, ps1, 2);
            l0 = l0 * c0 + ps0;
            l1 = l1 * c1 + ps1;
            #pragma unroll
            for (int nt = 0; nt < 8; nt++) {
                o[nt][0] *= c0; o[nt][1] *= c0;
                o[nt][2] *= c1; o[nt][3] *= c1;
            }
        }

        // ---- O += P @ V (fp16 m16n8k16; A-frags from C-frags, no shuffles) ----
        #pragma unroll
        for (int kc = 0; kc < 4; kc++) {
            unsigned pa[4];
            pa[0] = pack16(s[2 * kc][0],     s[2 * kc][1]);
            pa[1] = pack16(s[2 * kc][2],     s[2 * kc][3]);
            pa[2] = pack16(s[2 * kc + 1][0], s[2 * kc + 1][1]);
            pa[3] = pack16(s[2 * kc + 1][2], s[2 * kc + 1][3]);
            #pragma unroll
            for (int nt = 0; nt < 8; nt++) {
                const unsigned* vr = &Vt[(8 * nt + g) * VTSTR + 8 * kc + t];
                mma16(o[nt], pa, vr[0], vr[4]);
            }
        }
    }

    // ---- normalize + write ctx [b][s][e], e = h*64 + d ----
    const float inv0 = 1.f / l0, inv1 = 1.f / l1;
    float* c0p = &ctx[(b * S_LEN + r0) * E_DIM + h * DHEAD + t * 2];
    float* c1p = &ctx[(b * S_LEN + r0 + 8) * E_DIM + h * DHEAD + t * 2];
    #pragma unroll
    for (int nt = 0; nt < 8; nt++) {
        *reinterpret_cast<float2*>(&c0p[nt * 8]) =
            make_float2(o[nt][0] * inv0, o[nt][1] * inv0);
        *reinterpret_cast<float2*>(&c1p[nt * 8]) =
            make_float2(o[nt][2] * inv1, o[nt][3] * inv1);
    }
}

// =====================================================================
extern "C" void kernel_launch(void* const* d_in, const int* in_sizes, int n_in,
                              void* d_out, int out_size)
{
    const float* q    = (const float*)d_in[0];
    const float* k    = (const float*)d_in[1];
    const float* v    = (const float*)d_in[2];
    const int*   mask = (const int*)  d_in[3];
    const float* Wqkv = (const float*)d_in[4];
    const float* bqkv = (const float*)d_in[5];
    const float* Wout = (const float*)d_in[6];
    const float* bout = (const float*)d_in[7];
    float* out = (float*)d_out;
    (void)in_sizes; (void)n_in; (void)out_size;

    float *Qp, *Kp, *Vp, *ctx;
    cudaGetSymbolAddress((void**)&Qp,  g_Qp);
    cudaGetSymbolAddress((void**)&Kp,  g_Kp);
    cudaGetSymbolAddress((void**)&Vp,  g_Vp);
    cudaGetSymbolAddress((void**)&ctx, g_ctx);

    // fused QKV projection (tf32 tensor cores, 2xTF32 A-split)
    tf32_qkv_kernel<<<dim3(24, MROWS / 128), 256>>>(q, k, v, Wqkv, bqkv, Qp, Kp, Vp);

    // flash attention (tf32 QK + fp16 PV tensor cores)
    attn_kernel<<<dim3(S_LEN / 128, NHEAD, BATCH), 256>>>(Qp, Kp, Vp, mask, ctx);

    // output projection (tf32 tensor cores)
    tf32_out_kernel<<<dim3(E_DIM / 128, MROWS / 128), 256>>>(ctx, Wout, bout, out);
}